// round 2
// baseline (speedup 1.0000x reference)
#include <cuda_runtime.h>
#include <math_constants.h>

// MAM dense: C[n,j] = max_k(x[n,k]*w[j,k]) + min_k(x[n,k]*w[j,k]) + bias[j]
// x: [2048, 512] f32, w: [256, 512] f32, bias: [256] f32, out: [2048, 256] f32
//
// R2: K-split 2. alu pipe (FMNMX) is the binding resource; R1's 128-CTA grid
// left 20 SMs idle and ran 1 CTA/SM (issue=60%). 256 CTAs -> 2 CTAs on most
// SMs, 16 warps, no idle SMs. Partial max/min to device scratch, tiny combine
// kernel adds bias.

constexpr int IN_F  = 512;
constexpr int OUT_F = 256;
constexpr int NROWS = 2048;

constexpr int BN = 64;    // n-tile per block
constexpr int BJ = 64;    // j-tile per block
constexpr int KB = 32;    // k-chunk
constexpr int NSPLIT = 2; // k-splits
constexpr int KSPL = IN_F / NSPLIT;  // 256 per split
constexpr int THREADS = 256;

// Scratch for partial reductions: [split][n][j]
__device__ float g_pmax[NSPLIT * NROWS * OUT_F];
__device__ float g_pmin[NSPLIT * NROWS * OUT_F];

__global__ __launch_bounds__(THREADS)
void mam_partial_kernel(const float* __restrict__ x,
                        const float* __restrict__ w)
{
    __shared__ float xs[BN][KB + 1];
    __shared__ float ws[BJ][KB + 1];

    const int tid = threadIdx.x;
    const int tj  = tid & 15;   // 0..15 -> j groups of 4
    const int tn  = tid >> 4;   // 0..15 -> n groups of 4
    const int n0  = blockIdx.y * BN;
    const int j0  = blockIdx.x * BJ;
    const int ks  = blockIdx.z * KSPL;   // k range [ks, ks+KSPL)

    float maxv[4][4], minv[4][4];
#pragma unroll
    for (int i = 0; i < 4; i++)
#pragma unroll
        for (int jj = 0; jj < 4; jj++) {
            maxv[i][jj] = -CUDART_INF_F;
            minv[i][jj] =  CUDART_INF_F;
        }

    // Loader mapping: tile is 64 rows x 32 k = 512 float4.
    // Thread owns float4 f = tid and f = tid + 256.
    const int rA = tid >> 3,         kqA = tid & 7;
    const int rB = (tid + 256) >> 3, kqB = (tid + 256) & 7;

    // Prefetch chunk 0.
    float4 xrA, xrB, wrA, wrB;
    xrA = *reinterpret_cast<const float4*>(&x[(n0 + rA) * IN_F + ks + kqA * 4]);
    xrB = *reinterpret_cast<const float4*>(&x[(n0 + rB) * IN_F + ks + kqB * 4]);
    wrA = *reinterpret_cast<const float4*>(&w[(j0 + rA) * IN_F + ks + kqA * 4]);
    wrB = *reinterpret_cast<const float4*>(&w[(j0 + rB) * IN_F + ks + kqB * 4]);

    for (int k0 = ks; k0 < ks + KSPL; k0 += KB) {
        xs[rA][kqA * 4 + 0] = xrA.x; xs[rA][kqA * 4 + 1] = xrA.y;
        xs[rA][kqA * 4 + 2] = xrA.z; xs[rA][kqA * 4 + 3] = xrA.w;
        xs[rB][kqB * 4 + 0] = xrB.x; xs[rB][kqB * 4 + 1] = xrB.y;
        xs[rB][kqB * 4 + 2] = xrB.z; xs[rB][kqB * 4 + 3] = xrB.w;
        ws[rA][kqA * 4 + 0] = wrA.x; ws[rA][kqA * 4 + 1] = wrA.y;
        ws[rA][kqA * 4 + 2] = wrA.z; ws[rA][kqA * 4 + 3] = wrA.w;
        ws[rB][kqB * 4 + 0] = wrB.x; ws[rB][kqB * 4 + 1] = wrB.y;
        ws[rB][kqB * 4 + 2] = wrB.z; ws[rB][kqB * 4 + 3] = wrB.w;
        __syncthreads();

        const int kn = k0 + KB;
        if (kn < ks + KSPL) {
            xrA = *reinterpret_cast<const float4*>(&x[(n0 + rA) * IN_F + kn + kqA * 4]);
            xrB = *reinterpret_cast<const float4*>(&x[(n0 + rB) * IN_F + kn + kqB * 4]);
            wrA = *reinterpret_cast<const float4*>(&w[(j0 + rA) * IN_F + kn + kqA * 4]);
            wrB = *reinterpret_cast<const float4*>(&w[(j0 + rB) * IN_F + kn + kqB * 4]);
        }

#pragma unroll
        for (int k = 0; k < KB; k++) {
            float a[4], b[4];
#pragma unroll
            for (int i = 0; i < 4; i++)  a[i]  = xs[tn * 4 + i][k];
#pragma unroll
            for (int jj = 0; jj < 4; jj++) b[jj] = ws[tj * 4 + jj][k];
#pragma unroll
            for (int i = 0; i < 4; i++)
#pragma unroll
                for (int jj = 0; jj < 4; jj++) {
                    const float p = a[i] * b[jj];
                    maxv[i][jj] = fmaxf(maxv[i][jj], p);
                    minv[i][jj] = fminf(minv[i][jj], p);
                }
        }
        __syncthreads();
    }

    // Write partials for this split.
    float* pmax = &g_pmax[blockIdx.z * (NROWS * OUT_F)];
    float* pmin = &g_pmin[blockIdx.z * (NROWS * OUT_F)];
#pragma unroll
    for (int i = 0; i < 4; i++) {
        const int n = n0 + tn * 4 + i;
#pragma unroll
        for (int jj = 0; jj < 4; jj++) {
            const int j = j0 + tj * 4 + jj;
            pmax[n * OUT_F + j] = maxv[i][jj];
            pmin[n * OUT_F + j] = minv[i][jj];
        }
    }
}

__global__ __launch_bounds__(256)
void mam_combine_kernel(const float* __restrict__ bias,
                        float* __restrict__ out)
{
    // One float4 per thread over [2048, 256].
    const int v = blockIdx.x * blockDim.x + threadIdx.x;  // float4 index
    const int total4 = NROWS * OUT_F / 4;
    if (v >= total4) return;

    const float4 ma = reinterpret_cast<const float4*>(g_pmax)[v];
    const float4 mb = reinterpret_cast<const float4*>(g_pmax + NROWS * OUT_F)[v];
    const float4 na = reinterpret_cast<const float4*>(g_pmin)[v];
    const float4 nb = reinterpret_cast<const float4*>(g_pmin + NROWS * OUT_F)[v];
    const int j4 = v & (OUT_F / 4 - 1);
    const float4 bz = reinterpret_cast<const float4*>(bias)[j4];

    float4 r;
    r.x = fmaxf(ma.x, mb.x) + fminf(na.x, nb.x) + bz.x;
    r.y = fmaxf(ma.y, mb.y) + fminf(na.y, nb.y) + bz.y;
    r.z = fmaxf(ma.z, mb.z) + fminf(na.z, nb.z) + bz.z;
    r.w = fmaxf(ma.w, mb.w) + fminf(na.w, nb.w) + bz.w;
    reinterpret_cast<float4*>(out)[v] = r;
}

extern "C" void kernel_launch(void* const* d_in, const int* in_sizes, int n_in,
                              void* d_out, int out_size)
{
    const float* x    = (const float*)d_in[0];   // [2048, 512]
    const float* w    = (const float*)d_in[1];   // [256, 512]
    const float* bias = (const float*)d_in[2];   // [256]
    float* out        = (float*)d_out;           // [2048, 256]

    dim3 grid(OUT_F / BJ, NROWS / BN, NSPLIT);   // (4, 32, 2) = 256 CTAs
    mam_partial_kernel<<<grid, THREADS>>>(x, w);

    const int total4 = NROWS * OUT_F / 4;        // 131072
    mam_combine_kernel<<<total4 / 256, 256>>>(bias, out);
}

// round 3
// speedup vs baseline: 1.2573x; 1.2573x over previous
#include <cuda_runtime.h>
#include <math_constants.h>

// MAM dense: C[n,j] = max_k(x[n,k]*w[j,k]) + min_k(x[n,k]*w[j,k]) + bias[j]
// x: [2048, 512] f32, w: [256, 512] f32, bias: [256] f32, out: [2048, 256] f32
//
// R3: load-balance fix. Binding resource = alu pipe (FMNMX), floor 56.7K
// SMSP-cycles. R1/R2 both hit a 65.5K per-SM max from coarse-grain CTA
// imbalance (128 CTAs / 1 wave, or 256 CTAs all-resident 2-vs-1).
// Fix: 1024 small CTAs (tile 32x16, full K) -> 7-vs-6 per-SM split = 1.2%
// over floor. No k-split, no combine kernel. Inner loop k-major smem:
// 1 LDS.128 + 1 LDS + 4 FMUL + 8 FMNMX per k (14 issue vs 16 alu cycles).

constexpr int IN_F  = 512;
constexpr int OUT_F = 256;
constexpr int NROWS = 2048;

constexpr int BN = 32;    // n-tile
constexpr int BJ = 16;    // j-tile
constexpr int KB = 32;    // k-chunk
constexpr int THREADS = 128;

constexpr int XS_LD = 36; // padded lead (mult of 4 keeps LDS.128 aligned, 2-way STS conflict max)
constexpr int WS_LD = 17; // conflict-free for both STS scatter and per-k reads

__global__ __launch_bounds__(THREADS, 8)
void mam_dense_kernel(const float* __restrict__ x,
                      const float* __restrict__ w,
                      const float* __restrict__ bias,
                      float* __restrict__ out)
{
    __shared__ float xs[KB][XS_LD];  // [k][n]  (transposed for vector a-loads)
    __shared__ float ws[KB][WS_LD];  // [k][j]

    const int tid = threadIdx.x;
    const int tj  = tid & 15;        // j within tile
    const int tn  = tid >> 4;        // 0..7 -> n group of 4
    const int j0  = blockIdx.x * BJ;
    const int n0  = blockIdx.y * BN;

    // Loader mapping:
    //  x tile: 32 rows x 32 k = 256 float4; thread owns rows xn and xn+16 at k-quad xk.
    //  w tile: 16 rows x 32 k = 128 float4; one per thread.
    const int xn = tid >> 3;             // 0..15
    const int xk = (tid & 7) * 4;        // 0,4,...,28
    const int wj = tid >> 3;             // 0..15
    const int wk = (tid & 7) * 4;

    float maxv[4], minv[4];
#pragma unroll
    for (int i = 0; i < 4; i++) { maxv[i] = -CUDART_INF_F; minv[i] = CUDART_INF_F; }

    // Prefetch chunk 0 into registers.
    float4 xr0 = *reinterpret_cast<const float4*>(&x[(n0 + xn     ) * IN_F + xk]);
    float4 xr1 = *reinterpret_cast<const float4*>(&x[(n0 + xn + 16) * IN_F + xk]);
    float4 wr  = *reinterpret_cast<const float4*>(&w[(j0 + wj     ) * IN_F + wk]);

    for (int k0 = 0; k0 < IN_F; k0 += KB) {
        // Scatter prefetched regs into k-major smem.
        xs[xk + 0][xn]      = xr0.x; xs[xk + 1][xn]      = xr0.y;
        xs[xk + 2][xn]      = xr0.z; xs[xk + 3][xn]      = xr0.w;
        xs[xk + 0][xn + 16] = xr1.x; xs[xk + 1][xn + 16] = xr1.y;
        xs[xk + 2][xn + 16] = xr1.z; xs[xk + 3][xn + 16] = xr1.w;
        ws[wk + 0][wj] = wr.x; ws[wk + 1][wj] = wr.y;
        ws[wk + 2][wj] = wr.z; ws[wk + 3][wj] = wr.w;
        __syncthreads();

        // Prefetch next chunk while computing this one.
        const int kn = k0 + KB;
        if (kn < IN_F) {
            xr0 = *reinterpret_cast<const float4*>(&x[(n0 + xn     ) * IN_F + kn + xk]);
            xr1 = *reinterpret_cast<const float4*>(&x[(n0 + xn + 16) * IN_F + kn + xk]);
            wr  = *reinterpret_cast<const float4*>(&w[(j0 + wj     ) * IN_F + kn + wk]);
        }

#pragma unroll
        for (int k = 0; k < KB; k++) {
            const float4 av = *reinterpret_cast<const float4*>(&xs[k][tn * 4]);
            const float  b  = ws[k][tj];
            float p;
            p = av.x * b; maxv[0] = fmaxf(maxv[0], p); minv[0] = fminf(minv[0], p);
            p = av.y * b; maxv[1] = fmaxf(maxv[1], p); minv[1] = fminf(minv[1], p);
            p = av.z * b; maxv[2] = fmaxf(maxv[2], p); minv[2] = fminf(minv[2], p);
            p = av.w * b; maxv[3] = fmaxf(maxv[3], p); minv[3] = fminf(minv[3], p);
        }
        __syncthreads();
    }

    // Epilogue: C = max + min + bias.
    const float bj = bias[j0 + tj];
#pragma unroll
    for (int i = 0; i < 4; i++) {
        const int n = n0 + tn * 4 + i;
        out[n * OUT_F + j0 + tj] = maxv[i] + minv[i] + bj;
    }
}

extern "C" void kernel_launch(void* const* d_in, const int* in_sizes, int n_in,
                              void* d_out, int out_size)
{
    const float* x    = (const float*)d_in[0];   // [2048, 512]
    const float* w    = (const float*)d_in[1];   // [256, 512]
    const float* bias = (const float*)d_in[2];   // [256]
    float* out        = (float*)d_out;           // [2048, 256]

    dim3 grid(OUT_F / BJ, NROWS / BN);           // (16, 64) = 1024 CTAs
    mam_dense_kernel<<<grid, THREADS>>>(x, w, bias, out);
}